// round 4
// baseline (speedup 1.0000x reference)
#include <cuda_runtime.h>
#include <math.h>

// Honest per-element evaluation (fallback; used only when the zero-bound
// doesn't hold for the parameter set or for a given element).
__device__ __forceinline__ float fuzzy_eval(float x,
                                            const float* __restrict__ fd,
                                            const float* __restrict__ sigma,
                                            int nparam) {
    float s = 0.0f;
    for (int j = 0; j < nparam; j++) {
        float sg = sigma[j];
        float d  = (x - fd[j]) / (sg * sg);
        s += sqrtf(d);          // NaN if d < 0, propagates
    }
    float o = expf(-s);
    if (isnan(o)) o = x;        // reference's NaN fallback
    return o;
}

// Zero-bound (single pass):
//   C0 = sum_j sqrt((0 - fd_j)/sigma_j^2)
// If any fd_j > 0, its term is NaN -> C0 is NaN -> fast path disabled.
// Otherwise, for x >= 0 every term sqrt((x - fd_j)/sigma_j^2) is monotone
// increasing in x (and fd_j <= 0 <= x), so s(x) >= C0 with all radicands
// >= 0 (no NaN possible). expf(-s) underflows to exactly 0.0f once
// s >= ~104.3; threshold 106 gives margin.
//
// Block shape: 1024 threads. nparam == 1024 here, so the bound reduction is
// exactly one scalar param load + one sqrt per thread, then one shuffle tree
// + one barrier. Each thread also handles exactly one x element.
__global__ void __launch_bounds__(1024)
fuzzy_fused_kernel(const float* __restrict__ x,
                   const float* __restrict__ fd,
                   const float* __restrict__ sigma,
                   float* __restrict__ out,
                   int n, int nparam) {
    const int tid  = threadIdx.x;
    const int lane = tid & 31;
    const int wid  = tid >> 5;
    const int gid  = blockIdx.x * 1024 + tid;

    // Issue the x load FIRST so its DRAM latency overlaps the reduction.
    float xv = 0.0f;
    const bool valid = (gid < n);
    if (valid) xv = x[gid];

    __shared__ float sred[32];

    // ---- C0 partial: one param per thread (loop for generic nparam) ----
    float acc = 0.0f;
    for (int j = tid; j < nparam; j += 1024) {
        float g = sigma[j];
        acc += sqrtf(-fd[j] / (g * g));
    }
#pragma unroll
    for (int o = 16; o > 0; o >>= 1)
        acc += __shfl_xor_sync(0xffffffffu, acc, o);
    if (lane == 0) sred[wid] = acc;
    __syncthreads();

    // Every thread sums the 32 warp partials in-register (pairwise tree,
    // no second barrier / broadcast round-trip).
    float t0 = sred[0]  + sred[1],  t1 = sred[2]  + sred[3];
    float t2 = sred[4]  + sred[5],  t3 = sred[6]  + sred[7];
    float t4 = sred[8]  + sred[9],  t5 = sred[10] + sred[11];
    float t6 = sred[12] + sred[13], t7 = sred[14] + sred[15];
    float u0 = sred[16] + sred[17], u1 = sred[18] + sred[19];
    float u2 = sred[20] + sred[21], u3 = sred[22] + sred[23];
    float u4 = sred[24] + sred[25], u5 = sred[26] + sred[27];
    float u6 = sred[28] + sred[29], u7 = sred[30] + sred[31];
    float C0 = ((t0 + t1) + (t2 + t3)) + ((t4 + t5) + (t6 + t7))
             + ((u0 + u1) + (u2 + u3)) + ((u4 + u5) + (u6 + u7));

    // NaN-safe: NaN >= 106 is false -> slow path.
    const bool fast_ok = (C0 >= 106.0f);

    if (!valid) return;
    out[gid] = (fast_ok && xv >= 0.0f)
                   ? 0.0f   // s(x) >= C0 >= 106 -> expf underflows to exact 0
                   : fuzzy_eval(xv, fd, sigma, nparam);
}

extern "C" void kernel_launch(void* const* d_in, const int* in_sizes, int n_in,
                              void* d_out, int out_size) {
    const float* x     = (const float*)d_in[0];
    const float* fd    = (const float*)d_in[1];
    const float* sigma = (const float*)d_in[2];
    float* out = (float*)d_out;

    const int n      = out_size;        // B samples
    const int nparam = in_sizes[1];     // I*O

    const int blocks = (n + 1023) / 1024;
    fuzzy_fused_kernel<<<blocks, 1024>>>(x, fd, sigma, out, n, nparam);
}